// round 1
// baseline (speedup 1.0000x reference)
#include <cuda_runtime.h>
#include <cstdint>

#define HEAD_NUM 8
#define DIM_QK 64
#define DIM_V 64
#define SPAN 64
#define STRIDE 4
#define R_SPAN 16   // SPAN / STRIDE

// Fixed problem shape (from reference): B=2, Lq=4096, Lkv=1024, D=512
#define BATCH 2
#define MAX_LQ 4096
#define MAX_LKV 1024
#define DMODEL 512

// Scratch (no cudaMalloc allowed) — ~40 MB total
__device__ __align__(16) float g_Q  [BATCH * MAX_LQ  * DMODEL];
__device__ __align__(16) float g_K  [BATCH * MAX_LKV * DMODEL];
__device__ __align__(16) float g_V  [BATCH * MAX_LKV * DMODEL];
__device__ __align__(16) float g_ctx[BATCH * MAX_LQ  * DMODEL];

// ---------------------------------------------------------------------------
// Classic 128x128x8 register-tiled fp32 SGEMM. C[M,N] = A[M,K] * B[K,N].
// Requires M%128==0, N%128==0, K%8==0. All row-major.
// ---------------------------------------------------------------------------
__global__ __launch_bounds__(256) void sgemm128(const float* __restrict__ A,
                                                const float* __restrict__ B,
                                                float* __restrict__ C,
                                                int M, int N, int K) {
    __shared__ float As[8][128];   // transposed A tile
    __shared__ float Bs[8][128];

    const int tid  = threadIdx.x;          // 0..255
    const int ty   = tid >> 4;             // 0..15 (row group)
    const int tx   = tid & 15;             // 0..15 (col group)

    const int cRow0 = blockIdx.y * 128;
    const int cCol0 = blockIdx.x * 128;

    // A tile loads: 128 rows x 8 cols, 2 float4 per row -> 256 float4
    const int aRow = tid >> 1;
    const int aCol = (tid & 1) * 4;
    // B tile loads: 8 rows x 128 cols -> 256 float4
    const int bRow = tid >> 5;
    const int bCol = (tid & 31) * 4;

    const float* Ap = A + (size_t)cRow0 * K;
    const float* Bp = B + cCol0;

    float acc[8][8];
    #pragma unroll
    for (int i = 0; i < 8; i++)
        #pragma unroll
        for (int j = 0; j < 8; j++) acc[i][j] = 0.f;

    for (int k0 = 0; k0 < K; k0 += 8) {
        float4 a4 = *(const float4*)(Ap + (size_t)aRow * K + k0 + aCol);
        As[aCol + 0][aRow] = a4.x;
        As[aCol + 1][aRow] = a4.y;
        As[aCol + 2][aRow] = a4.z;
        As[aCol + 3][aRow] = a4.w;
        float4 b4 = *(const float4*)(Bp + (size_t)(k0 + bRow) * N + bCol);
        *(float4*)&Bs[bRow][bCol] = b4;
        __syncthreads();

        #pragma unroll
        for (int k = 0; k < 8; k++) {
            float ar[8], br[8];
            #pragma unroll
            for (int i = 0; i < 8; i++) ar[i] = As[k][ty * 8 + i];
            #pragma unroll
            for (int j = 0; j < 8; j++) br[j] = Bs[k][tx * 8 + j];
            #pragma unroll
            for (int i = 0; i < 8; i++)
                #pragma unroll
                for (int j = 0; j < 8; j++)
                    acc[i][j] += ar[i] * br[j];
        }
        __syncthreads();
    }

    #pragma unroll
    for (int i = 0; i < 8; i++) {
        float* crow = C + (size_t)(cRow0 + ty * 8 + i) * N + cCol0 + tx * 8;
        #pragma unroll
        for (int j = 0; j < 8; j += 4) {
            float4 v = make_float4(acc[i][j], acc[i][j+1], acc[i][j+2], acc[i][j+3]);
            *(float4*)(crow + j) = v;
        }
    }
}

// ---------------------------------------------------------------------------
// Sparse attention: one warp per (b, h, c). Each query attends to <=16 keys.
// Q,K,V layouts: [B, L, H*64] (natural GEMM output). ctx: [B, Lq, H*64].
// ---------------------------------------------------------------------------
__device__ __forceinline__ int floordiv_s(int a, int d) {
    // floor division for possibly-negative numerator, positive d
    return (a >= 0) ? (a / d) : -((-a + d - 1) / d);
}

__global__ __launch_bounds__(256) void sparse_attn(const float* __restrict__ Q,
                                                   const float* __restrict__ Kp,
                                                   const float* __restrict__ Vp,
                                                   float* __restrict__ ctx,
                                                   int Lq, int Lkv) {
    const int warp  = (blockIdx.x * blockDim.x + threadIdx.x) >> 5;
    const int lane  = threadIdx.x & 31;
    const int total = BATCH * HEAD_NUM * Lq;
    if (warp >= total) return;

    const int c = warp % Lq;
    const int h = (warp / Lq) % HEAD_NUM;
    const int b = warp / (Lq * HEAD_NUM);

    const float* qptr = Q + ((size_t)(b * Lq + c) * (HEAD_NUM * DIM_QK)) + h * DIM_QK;
    const float q0 = qptr[lane];
    const float q1 = qptr[lane + 32];

    const int fd = floordiv_s(SPAN - 1 - c, STRIDE);

    float scores[R_SPAN];
    int   cols[R_SPAN];
    bool  vmask[R_SPAN];

    #pragma unroll
    for (int r = 0; r < R_SPAN; r++) {
        const int col = r - fd;
        const int row = c - STRIDE * col;
        const bool v  = (row >= 0) && (row < SPAN) && (col >= 0) && (col < Lkv);
        const int qc  = min(max(col, 0), Lkv - 1);
        cols[r]  = qc;
        vmask[r] = v;

        const float* kptr = Kp + ((size_t)(b * Lkv + qc) * (HEAD_NUM * DIM_QK)) + h * DIM_QK;
        float p = q0 * kptr[lane] + q1 * kptr[lane + 32];
        #pragma unroll
        for (int off = 16; off > 0; off >>= 1)
            p += __shfl_xor_sync(0xffffffffu, p, off);
        scores[r] = v ? p * 0.125f : -1e30f;   // 1/sqrt(64) = 0.125
    }

    float m = -1e30f;
    #pragma unroll
    for (int r = 0; r < R_SPAN; r++) m = fmaxf(m, scores[r]);

    float w[R_SPAN];
    float s = 0.f;
    #pragma unroll
    for (int r = 0; r < R_SPAN; r++) {
        float e = vmask[r] ? __expf(scores[r] - m) : 0.f;
        w[r] = e;
        s += e;
    }
    const float inv = 1.f / s;

    float o0 = 0.f, o1 = 0.f;
    #pragma unroll
    for (int r = 0; r < R_SPAN; r++) {
        const float wr = w[r] * inv;
        const float* vptr = Vp + ((size_t)(b * Lkv + cols[r]) * (HEAD_NUM * DIM_V)) + h * DIM_V;
        o0 += wr * vptr[lane];
        o1 += wr * vptr[lane + 32];
    }

    float* optr = ctx + ((size_t)(b * Lq + c) * (HEAD_NUM * DIM_V)) + h * DIM_V;
    optr[lane]      = o0;
    optr[lane + 32] = o1;
}

// ---------------------------------------------------------------------------
// Launch
// ---------------------------------------------------------------------------
extern "C" void kernel_launch(void* const* d_in, const int* in_sizes, int n_in,
                              void* d_out, int out_size) {
    const float* q    = (const float*)d_in[0];
    const float* k    = (const float*)d_in[1];
    const float* v    = (const float*)d_in[2];
    const float* Wq   = (const float*)d_in[3];
    const float* Wk   = (const float*)d_in[4];
    const float* Wv   = (const float*)d_in[5];
    const float* Wout = (const float*)d_in[6];
    float* out = (float*)d_out;

    const int Lq  = in_sizes[0] / (BATCH * DMODEL);   // 4096
    const int Lkv = in_sizes[1] / (BATCH * DMODEL);   // 1024
    const int Mq  = BATCH * Lq;    // 8192
    const int Mkv = BATCH * Lkv;   // 2048

    float *gQ, *gK, *gV, *gC;
    cudaGetSymbolAddress((void**)&gQ, g_Q);
    cudaGetSymbolAddress((void**)&gK, g_K);
    cudaGetSymbolAddress((void**)&gV, g_V);
    cudaGetSymbolAddress((void**)&gC, g_ctx);

    dim3 blk(256);

    // Projections: [M,512] @ [512,512]
    sgemm128<<<dim3(DMODEL / 128, Mq  / 128), blk>>>(q, Wq, gQ, Mq,  DMODEL, DMODEL);
    sgemm128<<<dim3(DMODEL / 128, Mkv / 128), blk>>>(k, Wk, gK, Mkv, DMODEL, DMODEL);
    sgemm128<<<dim3(DMODEL / 128, Mkv / 128), blk>>>(v, Wv, gV, Mkv, DMODEL, DMODEL);

    // Sparse attention: one warp per (b,h,c)
    const int total_warps = BATCH * HEAD_NUM * Lq;        // 65536
    const int blocks = (total_warps * 32 + 255) / 256;    // 8192
    sparse_attn<<<blocks, blk>>>(gQ, gK, gV, gC, Lq, Lkv);

    // Output projection: [8192,512] @ [512,512]
    sgemm128<<<dim3(DMODEL / 128, Mq / 128), blk>>>(gC, Wout, out, Mq, DMODEL, DMODEL);
}

// round 3
// speedup vs baseline: 2.1601x; 2.1601x over previous
#include <cuda_runtime.h>
#include <cuda_bf16.h>
#include <cstdint>

#define HEAD_NUM 8
#define DIM_QK 64
#define DIM_V 64
#define SPAN 64
#define STRIDE 4
#define R_SPAN 16

#define BATCH 2
#define MAX_LQ 4096
#define MAX_LKV 1024
#define DMODEL 512
#define GK 1536          // 3 * DMODEL (split-K concatenation)
#define CHUNKS 24        // GK / 64

// ---------------------------------------------------------------------------
// Scratch (no cudaMalloc allowed)
// ---------------------------------------------------------------------------
__device__ __align__(16) __nv_bfloat16 g_Ab[BATCH * MAX_LQ * GK];   // activation splits
__device__ __align__(16) __nv_bfloat16 g_Wb[DMODEL * GK];           // weight split (transposed)
__device__ __align__(16) float g_Q[BATCH * MAX_LQ * DMODEL];
__device__ __align__(16) float g_K[BATCH * MAX_LKV * DMODEL];
__device__ __align__(16) float g_V[BATCH * MAX_LKV * DMODEL];

// ---------------------------------------------------------------------------
// Baseline-target PTX helpers (all sm_80/sm_90 baseline, OK for .target sm_103)
// ---------------------------------------------------------------------------
__device__ __forceinline__ uint32_t smem_u32(const void* p) {
    uint32_t a;
    asm("{ .reg .u64 t; cvta.to.shared.u64 t, %1; cvt.u32.u64 %0, t; }" : "=r"(a) : "l"(p));
    return a;
}
__device__ __forceinline__ void cp_async16(uint32_t saddr, const void* gaddr) {
    asm volatile("cp.async.cg.shared.global [%0], [%1], 16;" :: "r"(saddr), "l"(gaddr));
}
__device__ __forceinline__ void cp_commit() {
    asm volatile("cp.async.commit_group;" ::: "memory");
}
__device__ __forceinline__ void cp_wait1() {
    asm volatile("cp.async.wait_group 1;" ::: "memory");
}
__device__ __forceinline__ void cp_wait0() {
    asm volatile("cp.async.wait_group 0;" ::: "memory");
}
__device__ __forceinline__ void ldm_x4(uint32_t* r, uint32_t addr) {
    asm volatile("ldmatrix.sync.aligned.m8n8.x4.shared.b16 {%0,%1,%2,%3}, [%4];"
                 : "=r"(r[0]), "=r"(r[1]), "=r"(r[2]), "=r"(r[3]) : "r"(addr));
}
__device__ __forceinline__ void ldm_x2(uint32_t* r, uint32_t addr) {
    asm volatile("ldmatrix.sync.aligned.m8n8.x2.shared.b16 {%0,%1}, [%2];"
                 : "=r"(r[0]), "=r"(r[1]) : "r"(addr));
}
__device__ __forceinline__ void mma_bf16(float* c, const uint32_t* a, const uint32_t* b) {
    asm volatile("mma.sync.aligned.m16n8k16.row.col.f32.bf16.bf16.f32 "
                 "{%0,%1,%2,%3}, {%4,%5,%6,%7}, {%8,%9}, {%0,%1,%2,%3};"
                 : "+f"(c[0]), "+f"(c[1]), "+f"(c[2]), "+f"(c[3])
                 : "r"(a[0]), "r"(a[1]), "r"(a[2]), "r"(a[3]), "r"(b[0]), "r"(b[1]));
}
__device__ __forceinline__ uint32_t sw128(uint32_t off) {
    return off ^ ((off >> 3) & 0x70);
}

// ---------------------------------------------------------------------------
// bf16 HMMA GEMM: C[M,512] = A'[M,GK] * Bt'[512,GK]^T  (both K-major, row-major mem)
// CTA 128x128, 8 warps (2x4), warp tile 64x32, K-chunk 64, cp.async double-buffer.
// smem: A0 @0 (16KB), B0 @16KB, A1 @32KB, B1 @48KB. Total 64KB dynamic.
// ---------------------------------------------------------------------------
#define GEMM_SMEM 65536

__device__ __forceinline__ void issue_chunk(const __nv_bfloat16* __restrict__ A,
                                            const __nv_bfloat16* __restrict__ Bt,
                                            uint32_t sb, int row0, int col0,
                                            int chunk, int buf, int tid) {
    const int k0 = chunk * 64;
    const uint32_t aoff = buf ? 32768u : 0u;
    const uint32_t boff = aoff + 16384u;
    #pragma unroll
    for (int p = 0; p < 4; p++) {
        const int idx = tid + p * 256;       // 0..1023
        const int r = idx >> 3;              // 0..127
        const int c8 = idx & 7;              // 16B units within 128B row
        const uint32_t sw = sw128((uint32_t)(r * 128 + c8 * 16));
        cp_async16(sb + aoff + sw, A + (size_t)(row0 + r) * GK + k0 + c8 * 8);
        cp_async16(sb + boff + sw, Bt + (size_t)(col0 + r) * GK + k0 + c8 * 8);
    }
    cp_commit();
}

__global__ __launch_bounds__(256) void gemm_mma(const __nv_bfloat16* __restrict__ A,
                                                const __nv_bfloat16* __restrict__ Bt,
                                                float* __restrict__ C, int N) {
    extern __shared__ __align__(1024) char smem[];
    const uint32_t sb = smem_u32(smem);
    const int tid = threadIdx.x, wid = tid >> 5, lane = tid & 31;
    const int warpM = wid >> 2;      // 0..1
    const int warpN = wid & 3;       // 0..3
    const int row0 = blockIdx.y * 128, col0 = blockIdx.x * 128;

    float acc[4][4][4];
    #pragma unroll
    for (int mi = 0; mi < 4; mi++)
        #pragma unroll
        for (int ni = 0; ni < 4; ni++)
            #pragma unroll
            for (int j = 0; j < 4; j++) acc[mi][ni][j] = 0.f;

    // Precompute per-lane ldmatrix smem byte layout pieces
    const int a_row_in_warp = lane & 15;       // m within 16
    const int a_khalf = (lane >> 4) & 1;       // k 0/8
    const int b_row_in_tile = lane & 7;        // n within 8
    const int b_khalf = (lane >> 3) & 1;

    issue_chunk(A, Bt, sb, row0, col0, 0, 0, tid);

    for (int i = 0; i < CHUNKS; i++) {
        const int cur = i & 1;
        if (i + 1 < CHUNKS) {
            issue_chunk(A, Bt, sb, row0, col0, i + 1, cur ^ 1, tid);
            cp_wait1();
        } else {
            cp_wait0();
        }
        __syncthreads();

        const uint32_t aoff = cur ? 32768u : 0u;
        const uint32_t boff = aoff + 16384u;
        #pragma unroll
        for (int kk = 0; kk < 4; kk++) {
            uint32_t afrag[4][4], bfrag[4][2];
            #pragma unroll
            for (int mi = 0; mi < 4; mi++) {
                const int r = warpM * 64 + mi * 16 + a_row_in_warp;
                const uint32_t sw = sw128((uint32_t)(r * 128 + kk * 32 + a_khalf * 16));
                ldm_x4(afrag[mi], sb + aoff + sw);
            }
            #pragma unroll
            for (int ni = 0; ni < 4; ni++) {
                const int r = warpN * 32 + ni * 8 + b_row_in_tile;
                const uint32_t sw = sw128((uint32_t)(r * 128 + kk * 32 + b_khalf * 16));
                ldm_x2(bfrag[ni], sb + boff + sw);
            }
            #pragma unroll
            for (int mi = 0; mi < 4; mi++)
                #pragma unroll
                for (int ni = 0; ni < 4; ni++)
                    mma_bf16(acc[mi][ni], afrag[mi], bfrag[ni]);
        }
        __syncthreads();
    }

    // Epilogue: c0/c1 -> (m = l/4, n = 2(l%4)), c2/c3 -> (m = l/4 + 8)
    const int erow = lane >> 2;
    const int ecol = 2 * (lane & 3);
    #pragma unroll
    for (int mi = 0; mi < 4; mi++) {
        #pragma unroll
        for (int ni = 0; ni < 4; ni++) {
            const int r = row0 + warpM * 64 + mi * 16 + erow;
            const int c = col0 + warpN * 32 + ni * 8 + ecol;
            *(float2*)(C + (size_t)r * N + c) = make_float2(acc[mi][ni][0], acc[mi][ni][1]);
            *(float2*)(C + (size_t)(r + 8) * N + c) = make_float2(acc[mi][ni][2], acc[mi][ni][3]);
        }
    }
}

// ---------------------------------------------------------------------------
// Split conversions (fp32 -> bf16 hi/lo in concatenated-K layout)
// ---------------------------------------------------------------------------
struct __align__(8) bf4 { __nv_bfloat16 a, b, c, d; };

__device__ __forceinline__ void split1(float x, __nv_bfloat16& h, __nv_bfloat16& l) {
    h = __float2bfloat16(x);
    l = __float2bfloat16(x - __bfloat162float(h));
}

// activations: out[m][k]=hi, out[m][512+k]=hi, out[m][1024+k]=lo
__global__ __launch_bounds__(256) void split_act(const float4* __restrict__ in,
                                                 __nv_bfloat16* __restrict__ out, int M) {
    const int gid = blockIdx.x * 256 + threadIdx.x;
    if (gid >= M * 128) return;
    const int m = gid >> 7, c4 = gid & 127;
    float4 x = in[gid];
    bf4 hv, lv;
    split1(x.x, hv.a, lv.a); split1(x.y, hv.b, lv.b);
    split1(x.z, hv.c, lv.c); split1(x.w, hv.d, lv.d);
    __nv_bfloat16* base = out + (size_t)m * GK + c4 * 4;
    *(bf4*)(base) = hv;
    *(bf4*)(base + 512) = hv;
    *(bf4*)(base + 1024) = lv;
}

// weights (transpose + split): Wb[n][k]=hi(W[k][n]), Wb[n][512+k]=lo, Wb[n][1024+k]=hi
__global__ void split_wT(const float* __restrict__ W, __nv_bfloat16* __restrict__ Wb) {
    __shared__ float t[32][33];
    const int k = blockIdx.y * 32 + threadIdx.y;
    const int n = blockIdx.x * 32 + threadIdx.x;
    t[threadIdx.y][threadIdx.x] = W[k * DMODEL + n];
    __syncthreads();
    const int n2 = blockIdx.x * 32 + threadIdx.y;
    const int k2 = blockIdx.y * 32 + threadIdx.x;
    const float x = t[threadIdx.x][threadIdx.y];
    __nv_bfloat16 h, l;
    split1(x, h, l);
    __nv_bfloat16* o = Wb + (size_t)n2 * GK + k2;
    o[0] = h; o[512] = l; o[1024] = h;
}

// ---------------------------------------------------------------------------
// Sparse attention: one warp per (b, h, c). Writes split-bf16 ctx directly.
// ---------------------------------------------------------------------------
__device__ __forceinline__ int floordiv_s(int a, int d) {
    return (a >= 0) ? (a / d) : -((-a + d - 1) / d);
}

__global__ __launch_bounds__(256) void sparse_attn(const float* __restrict__ Q,
                                                   const float* __restrict__ Kp,
                                                   const float* __restrict__ Vp,
                                                   __nv_bfloat16* __restrict__ ctxb,
                                                   int Lq, int Lkv) {
    const int warp = (blockIdx.x * blockDim.x + threadIdx.x) >> 5;
    const int lane = threadIdx.x & 31;
    if (warp >= BATCH * HEAD_NUM * Lq) return;

    const int c = warp % Lq;
    const int h = (warp / Lq) % HEAD_NUM;
    const int b = warp / (Lq * HEAD_NUM);

    const int qoff = (b * Lq + c) * DMODEL + h * DIM_QK;
    const float q0 = __ldg(Q + qoff + lane);
    const float q1 = __ldg(Q + qoff + lane + 32);

    const int fd = floordiv_s(SPAN - 1 - c, STRIDE);
    const int kvbase = b * Lkv * DMODEL + h * DIM_QK;

    float scores[R_SPAN];
    int cols[R_SPAN];
    bool vmask[R_SPAN];

    #pragma unroll
    for (int r = 0; r < R_SPAN; r++) {
        const int col = r - fd;
        const int row = c - STRIDE * col;
        const bool v = (row >= 0) && (row < SPAN) && (col >= 0) && (col < Lkv);
        const int qc = min(max(col, 0), Lkv - 1);
        cols[r] = qc;
        vmask[r] = v;
        const float* kptr = Kp + kvbase + qc * DMODEL;
        float p = q0 * __ldg(kptr + lane) + q1 * __ldg(kptr + lane + 32);
        #pragma unroll
        for (int off = 16; off > 0; off >>= 1)
            p += __shfl_xor_sync(0xffffffffu, p, off);
        scores[r] = v ? p * 0.125f : -1e30f;
    }

    float m = -1e30f;
    #pragma unroll
    for (int r = 0; r < R_SPAN; r++) m = fmaxf(m, scores[r]);
    float w[R_SPAN];
    float s = 0.f;
    #pragma unroll
    for (int r = 0; r < R_SPAN; r++) {
        float e = vmask[r] ? __expf(scores[r] - m) : 0.f;
        w[r] = e;
        s += e;
    }
    const float inv = 1.f / s;

    float o0 = 0.f, o1 = 0.f;
    #pragma unroll
    for (int r = 0; r < R_SPAN; r++) {
        const float wr = w[r] * inv;
        const float* vptr = Vp + kvbase + cols[r] * DMODEL;
        o0 += wr * __ldg(vptr + lane);
        o1 += wr * __ldg(vptr + lane + 32);
    }

    __nv_bfloat16 h0, l0, h1, l1;
    split1(o0, h0, l0);
    split1(o1, h1, l1);
    __nv_bfloat16* base = ctxb + (size_t)(b * Lq + c) * GK + h * DIM_V;
    base[lane] = h0;            base[lane + 32] = h1;
    base[512 + lane] = h0;      base[512 + lane + 32] = h1;
    base[1024 + lane] = l0;     base[1024 + lane + 32] = l1;
}

// ---------------------------------------------------------------------------
// Launch
// ---------------------------------------------------------------------------
extern "C" void kernel_launch(void* const* d_in, const int* in_sizes, int n_in,
                              void* d_out, int out_size) {
    const float* q    = (const float*)d_in[0];
    const float* k    = (const float*)d_in[1];
    const float* v    = (const float*)d_in[2];
    const float* Wq   = (const float*)d_in[3];
    const float* Wk   = (const float*)d_in[4];
    const float* Wv   = (const float*)d_in[5];
    const float* Wout = (const float*)d_in[6];
    float* out = (float*)d_out;

    const int Lq  = in_sizes[0] / (BATCH * DMODEL);   // 4096
    const int Lkv = in_sizes[1] / (BATCH * DMODEL);   // 1024
    const int Mq  = BATCH * Lq;    // 8192
    const int Mkv = BATCH * Lkv;   // 2048

    __nv_bfloat16 *gAb, *gWb;
    float *gQ, *gK, *gV;
    cudaGetSymbolAddress((void**)&gAb, g_Ab);
    cudaGetSymbolAddress((void**)&gWb, g_Wb);
    cudaGetSymbolAddress((void**)&gQ, g_Q);
    cudaGetSymbolAddress((void**)&gK, g_K);
    cudaGetSymbolAddress((void**)&gV, g_V);

    cudaFuncSetAttribute(gemm_mma, cudaFuncAttributeMaxDynamicSharedMemorySize, GEMM_SMEM);

    const dim3 wgrid(16, 16), wblk(32, 32);

    // Q projection
    split_wT<<<wgrid, wblk>>>(Wq, gWb);
    split_act<<<(Mq * 128 + 255) / 256, 256>>>((const float4*)q, gAb, Mq);
    gemm_mma<<<dim3(4, Mq / 128), 256, GEMM_SMEM>>>(gAb, gWb, gQ, DMODEL);

    // K projection
    split_wT<<<wgrid, wblk>>>(Wk, gWb);
    split_act<<<(Mkv * 128 + 255) / 256, 256>>>((const float4*)k, gAb, Mkv);
    gemm_mma<<<dim3(4, Mkv / 128), 256, GEMM_SMEM>>>(gAb, gWb, gK, DMODEL);

    // V projection
    split_wT<<<wgrid, wblk>>>(Wv, gWb);
    split_act<<<(Mkv * 128 + 255) / 256, 256>>>((const float4*)v, gAb, Mkv);
    gemm_mma<<<dim3(4, Mkv / 128), 256, GEMM_SMEM>>>(gAb, gWb, gV, DMODEL);

    // Sparse attention (writes split ctx into gAb)
    const int total_warps = BATCH * HEAD_NUM * Lq;
    sparse_attn<<<(total_warps * 32 + 255) / 256, 256>>>(gQ, gK, gV, gAb, Lq, Lkv);

    // Output projection -> d_out
    split_wT<<<wgrid, wblk>>>(Wout, gWb);
    gemm_mma<<<dim3(4, Mq / 128), 256, GEMM_SMEM>>>(gAb, gWb, out, DMODEL);
}

// round 4
// speedup vs baseline: 2.5648x; 1.1874x over previous
#include <cuda_runtime.h>
#include <cuda_bf16.h>
#include <cstdint>

#define HEAD_NUM 8
#define DIM_QK 64
#define DIM_V 64
#define SPAN 64
#define STRIDE 4
#define R_SPAN 16

#define BATCH 2
#define MAX_LQ 4096
#define MAX_LKV 1024
#define DMODEL 512
#define GK 1536          // 3 * DMODEL (split-K concatenation)
#define CHUNKS 24        // GK / 64
#define WSTRIDE (DMODEL * GK)

// ---------------------------------------------------------------------------
// Scratch (no cudaMalloc allowed)
// ---------------------------------------------------------------------------
__device__ __align__(16) __nv_bfloat16 g_Ab[BATCH * MAX_LQ * GK];    // q-split, then ctx-split
__device__ __align__(16) __nv_bfloat16 g_Kb[BATCH * MAX_LKV * GK];   // k-split
__device__ __align__(16) __nv_bfloat16 g_Vb[BATCH * MAX_LKV * GK];   // v-split
__device__ __align__(16) __nv_bfloat16 g_Wb4[4 * WSTRIDE];           // 4 weight splits
__device__ __align__(16) float g_Q[BATCH * MAX_LQ * DMODEL];
__device__ __align__(16) float g_K[BATCH * MAX_LKV * DMODEL];
__device__ __align__(16) float g_V[BATCH * MAX_LKV * DMODEL];

// ---------------------------------------------------------------------------
// Baseline-target PTX helpers
// ---------------------------------------------------------------------------
__device__ __forceinline__ uint32_t smem_u32(const void* p) {
    uint32_t a;
    asm("{ .reg .u64 t; cvta.to.shared.u64 t, %1; cvt.u32.u64 %0, t; }" : "=r"(a) : "l"(p));
    return a;
}
__device__ __forceinline__ void cp_async16(uint32_t saddr, const void* gaddr) {
    asm volatile("cp.async.cg.shared.global [%0], [%1], 16;" :: "r"(saddr), "l"(gaddr));
}
__device__ __forceinline__ void cp_commit() { asm volatile("cp.async.commit_group;" ::: "memory"); }
__device__ __forceinline__ void cp_wait1() { asm volatile("cp.async.wait_group 1;" ::: "memory"); }
__device__ __forceinline__ void cp_wait0() { asm volatile("cp.async.wait_group 0;" ::: "memory"); }
__device__ __forceinline__ void ldm_x4(uint32_t* r, uint32_t addr) {
    asm volatile("ldmatrix.sync.aligned.m8n8.x4.shared.b16 {%0,%1,%2,%3}, [%4];"
                 : "=r"(r[0]), "=r"(r[1]), "=r"(r[2]), "=r"(r[3]) : "r"(addr));
}
__device__ __forceinline__ void ldm_x2(uint32_t* r, uint32_t addr) {
    asm volatile("ldmatrix.sync.aligned.m8n8.x2.shared.b16 {%0,%1}, [%2];"
                 : "=r"(r[0]), "=r"(r[1]) : "r"(addr));
}
__device__ __forceinline__ void mma_bf16(float* c, const uint32_t* a, const uint32_t* b) {
    asm volatile("mma.sync.aligned.m16n8k16.row.col.f32.bf16.bf16.f32 "
                 "{%0,%1,%2,%3}, {%4,%5,%6,%7}, {%8,%9}, {%0,%1,%2,%3};"
                 : "+f"(c[0]), "+f"(c[1]), "+f"(c[2]), "+f"(c[3])
                 : "r"(a[0]), "r"(a[1]), "r"(a[2]), "r"(a[3]), "r"(b[0]), "r"(b[1]));
}
__device__ __forceinline__ uint32_t sw128(uint32_t off) { return off ^ ((off >> 3) & 0x70); }

// ---------------------------------------------------------------------------
// GEMM tile worker: C[128,128] += A'[row0.., GK] * Bt'[col0.., GK]^T
// CTA 128x128, 8 warps (2x4), warp tile 64x32, K-chunk 64, cp.async dbl-buffer.
// ---------------------------------------------------------------------------
#define GEMM_SMEM 65536

__device__ __forceinline__ void issue_chunk(const __nv_bfloat16* __restrict__ A,
                                            const __nv_bfloat16* __restrict__ Bt,
                                            uint32_t sb, int row0, int col0,
                                            int chunk, int buf, int tid) {
    const int k0 = chunk * 64;
    const uint32_t aoff = buf ? 32768u : 0u;
    const uint32_t boff = aoff + 16384u;
    #pragma unroll
    for (int p = 0; p < 4; p++) {
        const int idx = tid + p * 256;
        const int r = idx >> 3;
        const int c8 = idx & 7;
        const uint32_t sw = sw128((uint32_t)(r * 128 + c8 * 16));
        cp_async16(sb + aoff + sw, A + (size_t)(row0 + r) * GK + k0 + c8 * 8);
        cp_async16(sb + boff + sw, Bt + (size_t)(col0 + r) * GK + k0 + c8 * 8);
    }
    cp_commit();
}

__device__ __forceinline__ void gemm_tile(const __nv_bfloat16* __restrict__ A,
                                          const __nv_bfloat16* __restrict__ Bt,
                                          float* __restrict__ C,
                                          int row0, int col0, uint32_t sb, int tid) {
    const int wid = tid >> 5, lane = tid & 31;
    const int warpM = wid >> 2, warpN = wid & 3;

    float acc[4][4][4];
    #pragma unroll
    for (int mi = 0; mi < 4; mi++)
        #pragma unroll
        for (int ni = 0; ni < 4; ni++)
            #pragma unroll
            for (int j = 0; j < 4; j++) acc[mi][ni][j] = 0.f;

    const int a_row_in_warp = lane & 15;
    const int a_khalf = (lane >> 4) & 1;
    const int b_row_in_tile = lane & 7;
    const int b_khalf = (lane >> 3) & 1;

    issue_chunk(A, Bt, sb, row0, col0, 0, 0, tid);

    for (int i = 0; i < CHUNKS; i++) {
        const int cur = i & 1;
        if (i + 1 < CHUNKS) {
            issue_chunk(A, Bt, sb, row0, col0, i + 1, cur ^ 1, tid);
            cp_wait1();
        } else {
            cp_wait0();
        }
        __syncthreads();

        const uint32_t aoff = cur ? 32768u : 0u;
        const uint32_t boff = aoff + 16384u;
        #pragma unroll
        for (int kk = 0; kk < 4; kk++) {
            uint32_t afrag[4][4], bfrag[4][2];
            #pragma unroll
            for (int mi = 0; mi < 4; mi++) {
                const int r = warpM * 64 + mi * 16 + a_row_in_warp;
                ldm_x4(afrag[mi], sb + aoff + sw128((uint32_t)(r * 128 + kk * 32 + a_khalf * 16)));
            }
            #pragma unroll
            for (int ni = 0; ni < 4; ni++) {
                const int r = warpN * 32 + ni * 8 + b_row_in_tile;
                ldm_x2(bfrag[ni], sb + boff + sw128((uint32_t)(r * 128 + kk * 32 + b_khalf * 16)));
            }
            #pragma unroll
            for (int mi = 0; mi < 4; mi++)
                #pragma unroll
                for (int ni = 0; ni < 4; ni++)
                    mma_bf16(acc[mi][ni], afrag[mi], bfrag[ni]);
        }
        __syncthreads();
    }

    const int erow = lane >> 2;
    const int ecol = 2 * (lane & 3);
    #pragma unroll
    for (int mi = 0; mi < 4; mi++) {
        #pragma unroll
        for (int ni = 0; ni < 4; ni++) {
            const int r = row0 + warpM * 64 + mi * 16 + erow;
            const int c = col0 + warpN * 32 + ni * 8 + ecol;
            *(float2*)(C + (size_t)r * DMODEL + c) = make_float2(acc[mi][ni][0], acc[mi][ni][1]);
            *(float2*)(C + (size_t)(r + 8) * DMODEL + c) = make_float2(acc[mi][ni][2], acc[mi][ni][3]);
        }
    }
}

// Fused Q/K/V projection GEMM: 384 tiles linearized (256 Q + 64 K + 64 V)
__global__ __launch_bounds__(256) void gemm_qkv(const __nv_bfloat16* __restrict__ Aq,
                                                const __nv_bfloat16* __restrict__ Ak,
                                                const __nv_bfloat16* __restrict__ Av,
                                                const __nv_bfloat16* __restrict__ Wb,
                                                float* __restrict__ Cq,
                                                float* __restrict__ Ck,
                                                float* __restrict__ Cv) {
    extern __shared__ __align__(1024) char smem[];
    int t = blockIdx.x;
    const __nv_bfloat16 *A, *B;
    float* C;
    if (t < 256) { A = Aq; B = Wb; C = Cq; }
    else if (t < 320) { t -= 256; A = Ak; B = Wb + WSTRIDE; C = Ck; }
    else { t -= 320; A = Av; B = Wb + 2 * WSTRIDE; C = Cv; }
    gemm_tile(A, B, C, (t >> 2) * 128, (t & 3) * 128, smem_u32(smem), threadIdx.x);
}

// Single GEMM (out projection)
__global__ __launch_bounds__(256) void gemm_one(const __nv_bfloat16* __restrict__ A,
                                                const __nv_bfloat16* __restrict__ Bt,
                                                float* __restrict__ C) {
    extern __shared__ __align__(1024) char smem[];
    gemm_tile(A, Bt, C, blockIdx.y * 128, blockIdx.x * 128, smem_u32(smem), threadIdx.x);
}

// ---------------------------------------------------------------------------
// Split conversions
// ---------------------------------------------------------------------------
struct __align__(8) bf4 { __nv_bfloat16 a, b, c, d; };

__device__ __forceinline__ void split1(float x, __nv_bfloat16& h, __nv_bfloat16& l) {
    h = __float2bfloat16(x);
    l = __float2bfloat16(x - __bfloat162float(h));
}

// all three activation splits in one launch
__global__ __launch_bounds__(256) void split_act_all(const float4* __restrict__ q,
                                                     const float4* __restrict__ k,
                                                     const float4* __restrict__ v,
                                                     __nv_bfloat16* __restrict__ outq,
                                                     __nv_bfloat16* __restrict__ outk,
                                                     __nv_bfloat16* __restrict__ outv,
                                                     int Mq, int Mkv) {
    const int gid = blockIdx.x * 256 + threadIdx.x;
    const int nq = Mq * 128, nkv = Mkv * 128;
    const float4* src;
    __nv_bfloat16* out;
    int loc;
    if (gid < nq) { src = q; out = outq; loc = gid; }
    else if (gid < nq + nkv) { src = k; out = outk; loc = gid - nq; }
    else if (gid < nq + 2 * nkv) { src = v; out = outv; loc = gid - nq - nkv; }
    else return;
    const int m = loc >> 7, c4 = loc & 127;
    float4 x = src[loc];
    bf4 hv, lv;
    split1(x.x, hv.a, lv.a); split1(x.y, hv.b, lv.b);
    split1(x.z, hv.c, lv.c); split1(x.w, hv.d, lv.d);
    __nv_bfloat16* base = out + (size_t)m * GK + c4 * 4;
    *(bf4*)(base) = hv;
    *(bf4*)(base + 512) = hv;
    *(bf4*)(base + 1024) = lv;
}

// all four weight splits in one launch (transpose + split)
__global__ void split_wT_all(const float* __restrict__ W0, const float* __restrict__ W1,
                             const float* __restrict__ W2, const float* __restrict__ W3,
                             __nv_bfloat16* __restrict__ Wb) {
    const float* W = (blockIdx.z == 0) ? W0 : (blockIdx.z == 1) ? W1 : (blockIdx.z == 2) ? W2 : W3;
    __nv_bfloat16* outW = Wb + (size_t)blockIdx.z * WSTRIDE;
    __shared__ float t[32][33];
    const int k = blockIdx.y * 32 + threadIdx.y;
    const int n = blockIdx.x * 32 + threadIdx.x;
    t[threadIdx.y][threadIdx.x] = W[k * DMODEL + n];
    __syncthreads();
    const int n2 = blockIdx.x * 32 + threadIdx.y;
    const int k2 = blockIdx.y * 32 + threadIdx.x;
    const float x = t[threadIdx.x][threadIdx.y];
    __nv_bfloat16 h, l;
    split1(x, h, l);
    __nv_bfloat16* o = outW + (size_t)n2 * GK + k2;
    o[0] = h; o[512] = l; o[1024] = h;
}

// ---------------------------------------------------------------------------
// Tiled sparse attention: CTA = 128 consecutive queries of one (b,h).
// Key window union across 128 queries = 47 cols -> stage K,V in smem.
// ---------------------------------------------------------------------------
#define QBLK 128
#define CTILE 48

__device__ __forceinline__ int floordiv_s(int a, int d) {
    return (a >= 0) ? (a / d) : -((-a + d - 1) / d);
}

__global__ __launch_bounds__(256) void sparse_attn_tiled(const float* __restrict__ Q,
                                                         const float* __restrict__ Kp,
                                                         const float* __restrict__ Vp,
                                                         __nv_bfloat16* __restrict__ ctxb,
                                                         int Lq, int Lkv) {
    __shared__ float Ks[CTILE][64];
    __shared__ float Vs[CTILE][64];

    const int bh = blockIdx.y;
    const int b = bh / HEAD_NUM;
    const int h = bh % HEAD_NUM;
    const int c0 = blockIdx.x * QBLK;
    const int tid = threadIdx.x;
    const int wid = tid >> 5, lane = tid & 31;

    // union of key windows: [max(0, c0/4 - 15), ...+47]
    const int colT0 = max(0, c0 / STRIDE - (R_SPAN - 1));

    // cooperative load: 48 cols x 16 float4 = 768 float4 per tensor
    for (int idx = tid; idx < CTILE * 16; idx += 256) {
        const int i = idx >> 4, d4 = idx & 15;
        const int col = colT0 + i;
        if (col < Lkv) {
            const size_t off = ((size_t)(b * Lkv + col) * DMODEL) + h * 64 + d4 * 4;
            *(float4*)&Ks[i][d4 * 4] = __ldg((const float4*)(Kp + off));
            *(float4*)&Vs[i][d4 * 4] = __ldg((const float4*)(Vp + off));
        }
    }
    __syncthreads();

    // each warp: 16 consecutive queries
    for (int qi = 0; qi < 16; qi++) {
        const int c = c0 + wid * 16 + qi;
        const int qoff = (b * Lq + c) * DMODEL + h * DIM_QK;
        const float q0 = __ldg(Q + qoff + lane);
        const float q1 = __ldg(Q + qoff + lane + 32);

        const int fd = floordiv_s(SPAN - 1 - c, STRIDE);

        float scores[R_SPAN];
        int iidx[R_SPAN];
        bool vmask[R_SPAN];

        #pragma unroll
        for (int r = 0; r < R_SPAN; r++) {
            const int col = r - fd;
            const int row = c - STRIDE * col;
            const bool vld = (row >= 0) && (row < SPAN) && (col >= 0) && (col < Lkv);
            const int ii = min(max(col - colT0, 0), CTILE - 1);
            iidx[r] = ii;
            vmask[r] = vld;
            float p = q0 * Ks[ii][lane] + q1 * Ks[ii][lane + 32];
            #pragma unroll
            for (int off = 16; off > 0; off >>= 1)
                p += __shfl_xor_sync(0xffffffffu, p, off);
            scores[r] = vld ? p * 0.125f : -1e30f;
        }

        float m = -1e30f;
        #pragma unroll
        for (int r = 0; r < R_SPAN; r++) m = fmaxf(m, scores[r]);
        float w[R_SPAN];
        float s = 0.f;
        #pragma unroll
        for (int r = 0; r < R_SPAN; r++) {
            float e = vmask[r] ? __expf(scores[r] - m) : 0.f;
            w[r] = e;
            s += e;
        }
        const float inv = 1.f / s;

        float o0 = 0.f, o1 = 0.f;
        #pragma unroll
        for (int r = 0; r < R_SPAN; r++) {
            const float wr = w[r] * inv;
            o0 += wr * Vs[iidx[r]][lane];
            o1 += wr * Vs[iidx[r]][lane + 32];
        }

        __nv_bfloat16 h0, l0, h1, l1;
        split1(o0, h0, l0);
        split1(o1, h1, l1);
        __nv_bfloat16* base = ctxb + (size_t)(b * Lq + c) * GK + h * DIM_V;
        base[lane] = h0;            base[lane + 32] = h1;
        base[512 + lane] = h0;      base[512 + lane + 32] = h1;
        base[1024 + lane] = l0;     base[1024 + lane + 32] = l1;
    }
}

// ---------------------------------------------------------------------------
// Launch
// ---------------------------------------------------------------------------
extern "C" void kernel_launch(void* const* d_in, const int* in_sizes, int n_in,
                              void* d_out, int out_size) {
    const float* q    = (const float*)d_in[0];
    const float* k    = (const float*)d_in[1];
    const float* v    = (const float*)d_in[2];
    const float* Wq   = (const float*)d_in[3];
    const float* Wk   = (const float*)d_in[4];
    const float* Wv   = (const float*)d_in[5];
    const float* Wout = (const float*)d_in[6];
    float* out = (float*)d_out;

    const int Lq  = in_sizes[0] / (BATCH * DMODEL);   // 4096
    const int Lkv = in_sizes[1] / (BATCH * DMODEL);   // 1024
    const int Mq  = BATCH * Lq;    // 8192
    const int Mkv = BATCH * Lkv;   // 2048

    __nv_bfloat16 *gAb, *gKb, *gVb, *gWb;
    float *gQ, *gK, *gV;
    cudaGetSymbolAddress((void**)&gAb, g_Ab);
    cudaGetSymbolAddress((void**)&gKb, g_Kb);
    cudaGetSymbolAddress((void**)&gVb, g_Vb);
    cudaGetSymbolAddress((void**)&gWb, g_Wb4);
    cudaGetSymbolAddress((void**)&gQ, g_Q);
    cudaGetSymbolAddress((void**)&gK, g_K);
    cudaGetSymbolAddress((void**)&gV, g_V);

    cudaFuncSetAttribute(gemm_qkv, cudaFuncAttributeMaxDynamicSharedMemorySize, GEMM_SMEM);
    cudaFuncSetAttribute(gemm_one, cudaFuncAttributeMaxDynamicSharedMemorySize, GEMM_SMEM);

    // 1. all weight splits
    split_wT_all<<<dim3(16, 16, 4), dim3(32, 32)>>>(Wq, Wk, Wv, Wout, gWb);

    // 2. all activation splits
    const int tot = (Mq + 2 * Mkv) * 128;
    split_act_all<<<(tot + 255) / 256, 256>>>((const float4*)q, (const float4*)k,
                                              (const float4*)v, gAb, gKb, gVb, Mq, Mkv);

    // 3. fused Q/K/V projection GEMM (256 + 64 + 64 tiles)
    gemm_qkv<<<384, 256, GEMM_SMEM>>>(gAb, gKb, gVb, gWb, gQ, gK, gV);

    // 4. tiled sparse attention (writes split ctx into gAb)
    sparse_attn_tiled<<<dim3(Lq / QBLK, BATCH * HEAD_NUM), 256>>>(gQ, gK, gV, gAb, Lq, Lkv);

    // 5. out projection -> d_out
    gemm_one<<<dim3(4, Mq / 128), 256, GEMM_SMEM>>>(gAb, gWb + 3 * (size_t)WSTRIDE, out);
}

// round 5
// speedup vs baseline: 2.9533x; 1.1514x over previous
#include <cuda_runtime.h>
#include <cuda_bf16.h>
#include <cstdint>

#define HEAD_NUM 8
#define DIM_QK 64
#define DIM_V 64
#define SPAN 64
#define STRIDE 4
#define R_SPAN 16

#define BATCH 2
#define MAX_LQ 4096
#define MAX_LKV 1024
#define DMODEL 512
#define GK 1536          // 3 * DMODEL (split-K concatenation)
#define CHUNKS 24        // GK / 64
#define WSTRIDE (DMODEL * GK)

// ---------------------------------------------------------------------------
// Scratch (no cudaMalloc allowed)
// ---------------------------------------------------------------------------
__device__ __align__(16) __nv_bfloat16 g_Ab[BATCH * MAX_LQ * GK];    // q-split, then ctx-split
__device__ __align__(16) __nv_bfloat16 g_Kb[BATCH * MAX_LKV * GK];   // k-split
__device__ __align__(16) __nv_bfloat16 g_Vb[BATCH * MAX_LKV * GK];   // v-split
__device__ __align__(16) __nv_bfloat16 g_Wb4[4 * WSTRIDE];           // 4 weight splits
__device__ __align__(16) float g_Q[BATCH * MAX_LQ * DMODEL];
__device__ __align__(16) float g_K[BATCH * MAX_LKV * DMODEL];
__device__ __align__(16) float g_V[BATCH * MAX_LKV * DMODEL];

// ---------------------------------------------------------------------------
// Baseline-target PTX helpers
// ---------------------------------------------------------------------------
__device__ __forceinline__ uint32_t smem_u32(const void* p) {
    uint32_t a;
    asm("{ .reg .u64 t; cvta.to.shared.u64 t, %1; cvt.u32.u64 %0, t; }" : "=r"(a) : "l"(p));
    return a;
}
__device__ __forceinline__ void cp_async16(uint32_t saddr, const void* gaddr) {
    asm volatile("cp.async.cg.shared.global [%0], [%1], 16;" :: "r"(saddr), "l"(gaddr));
}
__device__ __forceinline__ void cp_commit() { asm volatile("cp.async.commit_group;" ::: "memory"); }
__device__ __forceinline__ void cp_wait1() { asm volatile("cp.async.wait_group 1;" ::: "memory"); }
__device__ __forceinline__ void cp_wait0() { asm volatile("cp.async.wait_group 0;" ::: "memory"); }
__device__ __forceinline__ void ldm_x4(uint32_t* r, uint32_t addr) {
    asm volatile("ldmatrix.sync.aligned.m8n8.x4.shared.b16 {%0,%1,%2,%3}, [%4];"
                 : "=r"(r[0]), "=r"(r[1]), "=r"(r[2]), "=r"(r[3]) : "r"(addr));
}
__device__ __forceinline__ void ldm_x2(uint32_t* r, uint32_t addr) {
    asm volatile("ldmatrix.sync.aligned.m8n8.x2.shared.b16 {%0,%1}, [%2];"
                 : "=r"(r[0]), "=r"(r[1]) : "r"(addr));
}
__device__ __forceinline__ void mma_bf16(float* c, const uint32_t* a, const uint32_t* b) {
    asm volatile("mma.sync.aligned.m16n8k16.row.col.f32.bf16.bf16.f32 "
                 "{%0,%1,%2,%3}, {%4,%5,%6,%7}, {%8,%9}, {%0,%1,%2,%3};"
                 : "+f"(c[0]), "+f"(c[1]), "+f"(c[2]), "+f"(c[3])
                 : "r"(a[0]), "r"(a[1]), "r"(a[2]), "r"(a[3]), "r"(b[0]), "r"(b[1]));
}
__device__ __forceinline__ uint32_t sw128(uint32_t off) { return off ^ ((off >> 3) & 0x70); }

// ---------------------------------------------------------------------------
// GEMM tile worker: C[128,128] += A'[row0.., GK] * Bt'[col0.., GK]^T
// ---------------------------------------------------------------------------
#define GEMM_SMEM 65536

__device__ __forceinline__ void issue_chunk(const __nv_bfloat16* __restrict__ A,
                                            const __nv_bfloat16* __restrict__ Bt,
                                            uint32_t sb, int row0, int col0,
                                            int chunk, int buf, int tid) {
    const int k0 = chunk * 64;
    const uint32_t aoff = buf ? 32768u : 0u;
    const uint32_t boff = aoff + 16384u;
    #pragma unroll
    for (int p = 0; p < 4; p++) {
        const int idx = tid + p * 256;
        const int r = idx >> 3;
        const int c8 = idx & 7;
        const uint32_t sw = sw128((uint32_t)(r * 128 + c8 * 16));
        cp_async16(sb + aoff + sw, A + (size_t)(row0 + r) * GK + k0 + c8 * 8);
        cp_async16(sb + boff + sw, Bt + (size_t)(col0 + r) * GK + k0 + c8 * 8);
    }
    cp_commit();
}

__device__ __forceinline__ void gemm_tile(const __nv_bfloat16* __restrict__ A,
                                          const __nv_bfloat16* __restrict__ Bt,
                                          float* __restrict__ C,
                                          int row0, int col0, uint32_t sb, int tid) {
    const int wid = tid >> 5, lane = tid & 31;
    const int warpM = wid >> 2, warpN = wid & 3;

    float acc[4][4][4];
    #pragma unroll
    for (int mi = 0; mi < 4; mi++)
        #pragma unroll
        for (int ni = 0; ni < 4; ni++)
            #pragma unroll
            for (int j = 0; j < 4; j++) acc[mi][ni][j] = 0.f;

    const int a_row_in_warp = lane & 15;
    const int a_khalf = (lane >> 4) & 1;
    const int b_row_in_tile = lane & 7;
    const int b_khalf = (lane >> 3) & 1;

    issue_chunk(A, Bt, sb, row0, col0, 0, 0, tid);

    for (int i = 0; i < CHUNKS; i++) {
        const int cur = i & 1;
        if (i + 1 < CHUNKS) {
            issue_chunk(A, Bt, sb, row0, col0, i + 1, cur ^ 1, tid);
            cp_wait1();
        } else {
            cp_wait0();
        }
        __syncthreads();

        const uint32_t aoff = cur ? 32768u : 0u;
        const uint32_t boff = aoff + 16384u;
        #pragma unroll
        for (int kk = 0; kk < 4; kk++) {
            uint32_t afrag[4][4], bfrag[4][2];
            #pragma unroll
            for (int mi = 0; mi < 4; mi++) {
                const int r = warpM * 64 + mi * 16 + a_row_in_warp;
                ldm_x4(afrag[mi], sb + aoff + sw128((uint32_t)(r * 128 + kk * 32 + a_khalf * 16)));
            }
            #pragma unroll
            for (int ni = 0; ni < 4; ni++) {
                const int r = warpN * 32 + ni * 8 + b_row_in_tile;
                ldm_x2(bfrag[ni], sb + boff + sw128((uint32_t)(r * 128 + kk * 32 + b_khalf * 16)));
            }
            #pragma unroll
            for (int mi = 0; mi < 4; mi++)
                #pragma unroll
                for (int ni = 0; ni < 4; ni++)
                    mma_bf16(acc[mi][ni], afrag[mi], bfrag[ni]);
        }
        __syncthreads();
    }

    const int erow = lane >> 2;
    const int ecol = 2 * (lane & 3);
    #pragma unroll
    for (int mi = 0; mi < 4; mi++) {
        #pragma unroll
        for (int ni = 0; ni < 4; ni++) {
            const int r = row0 + warpM * 64 + mi * 16 + erow;
            const int c = col0 + warpN * 32 + ni * 8 + ecol;
            *(float2*)(C + (size_t)r * DMODEL + c) = make_float2(acc[mi][ni][0], acc[mi][ni][1]);
            *(float2*)(C + (size_t)(r + 8) * DMODEL + c) = make_float2(acc[mi][ni][2], acc[mi][ni][3]);
        }
    }
}

__global__ __launch_bounds__(256) void gemm_qkv(const __nv_bfloat16* __restrict__ Aq,
                                                const __nv_bfloat16* __restrict__ Ak,
                                                const __nv_bfloat16* __restrict__ Av,
                                                const __nv_bfloat16* __restrict__ Wb,
                                                float* __restrict__ Cq,
                                                float* __restrict__ Ck,
                                                float* __restrict__ Cv) {
    extern __shared__ __align__(1024) char smem[];
    int t = blockIdx.x;
    const __nv_bfloat16 *A, *B;
    float* C;
    if (t < 256) { A = Aq; B = Wb; C = Cq; }
    else if (t < 320) { t -= 256; A = Ak; B = Wb + WSTRIDE; C = Ck; }
    else { t -= 320; A = Av; B = Wb + 2 * WSTRIDE; C = Cv; }
    gemm_tile(A, B, C, (t >> 2) * 128, (t & 3) * 128, smem_u32(smem), threadIdx.x);
}

__global__ __launch_bounds__(256) void gemm_one(const __nv_bfloat16* __restrict__ A,
                                                const __nv_bfloat16* __restrict__ Bt,
                                                float* __restrict__ C) {
    extern __shared__ __align__(1024) char smem[];
    gemm_tile(A, Bt, C, blockIdx.y * 128, blockIdx.x * 128, smem_u32(smem), threadIdx.x);
}

// ---------------------------------------------------------------------------
// Split conversions
// ---------------------------------------------------------------------------
struct __align__(8) bf4 { __nv_bfloat16 a, b, c, d; };

__device__ __forceinline__ void split1(float x, __nv_bfloat16& h, __nv_bfloat16& l) {
    h = __float2bfloat16(x);
    l = __float2bfloat16(x - __bfloat162float(h));
}

__global__ __launch_bounds__(256) void split_act_all(const float4* __restrict__ q,
                                                     const float4* __restrict__ k,
                                                     const float4* __restrict__ v,
                                                     __nv_bfloat16* __restrict__ outq,
                                                     __nv_bfloat16* __restrict__ outk,
                                                     __nv_bfloat16* __restrict__ outv,
                                                     int Mq, int Mkv) {
    const int gid = blockIdx.x * 256 + threadIdx.x;
    const int nq = Mq * 128, nkv = Mkv * 128;
    const float4* src;
    __nv_bfloat16* out;
    int loc;
    if (gid < nq) { src = q; out = outq; loc = gid; }
    else if (gid < nq + nkv) { src = k; out = outk; loc = gid - nq; }
    else if (gid < nq + 2 * nkv) { src = v; out = outv; loc = gid - nq - nkv; }
    else return;
    const int m = loc >> 7, c4 = loc & 127;
    float4 x = src[loc];
    bf4 hv, lv;
    split1(x.x, hv.a, lv.a); split1(x.y, hv.b, lv.b);
    split1(x.z, hv.c, lv.c); split1(x.w, hv.d, lv.d);
    __nv_bfloat16* base = out + (size_t)m * GK + c4 * 4;
    *(bf4*)(base) = hv;
    *(bf4*)(base + 512) = hv;
    *(bf4*)(base + 1024) = lv;
}

__global__ void split_wT_all(const float* __restrict__ W0, const float* __restrict__ W1,
                             const float* __restrict__ W2, const float* __restrict__ W3,
                             __nv_bfloat16* __restrict__ Wb) {
    const float* W = (blockIdx.z == 0) ? W0 : (blockIdx.z == 1) ? W1 : (blockIdx.z == 2) ? W2 : W3;
    __nv_bfloat16* outW = Wb + (size_t)blockIdx.z * WSTRIDE;
    __shared__ float t[32][33];
    const int k = blockIdx.y * 32 + threadIdx.y;
    const int n = blockIdx.x * 32 + threadIdx.x;
    t[threadIdx.y][threadIdx.x] = W[k * DMODEL + n];
    __syncthreads();
    const int n2 = blockIdx.x * 32 + threadIdx.y;
    const int k2 = blockIdx.y * 32 + threadIdx.x;
    const float x = t[threadIdx.x][threadIdx.y];
    __nv_bfloat16 h, l;
    split1(x, h, l);
    __nv_bfloat16* o = outW + (size_t)n2 * GK + k2;
    o[0] = h; o[512] = l; o[1024] = h;
}

// ---------------------------------------------------------------------------
// Sparse attention v2: key-per-lane scores, float2-per-lane V accumulation.
// CTA = 128 consecutive queries of one (b,h). K tile transposed-free in smem:
// Ks4[col][d4] float4 with odd stride 17 (conflict-free column access).
// ---------------------------------------------------------------------------
#define QBLK 128
#define CTILE 48

__device__ __forceinline__ int floordiv_s(int a, int d) {
    return (a >= 0) ? (a / d) : -((-a + d - 1) / d);
}

__global__ __launch_bounds__(256) void sparse_attn_v2(const float* __restrict__ Q,
                                                      const float* __restrict__ Kp,
                                                      const float* __restrict__ Vp,
                                                      __nv_bfloat16* __restrict__ ctxb,
                                                      int Lq, int Lkv) {
    __shared__ float4 Ks4[CTILE][17];     // [col][d4], odd stride -> conflict-free
    __shared__ float2 Vs2[CTILE][32];     // [col][lane], dims (2l, 2l+1)

    const int bh = blockIdx.y;
    const int b = bh / HEAD_NUM;
    const int h = bh % HEAD_NUM;
    const int c0 = blockIdx.x * QBLK;
    const int tid = threadIdx.x;
    const int wid = tid >> 5, lane = tid & 31;
    const int rlane = lane & 15;          // key index within half-warp
    const int half = lane >> 4;

    const int colT0 = max(0, c0 / STRIDE - (R_SPAN - 1));

    // K tile: 48 cols x 16 float4 (coalesced gmem, conflict-free smem writes)
    for (int idx = tid; idx < CTILE * 16; idx += 256) {
        const int col = idx >> 4, d4 = idx & 15;
        if (colT0 + col < Lkv) {
            const size_t off = ((size_t)(b * Lkv + colT0 + col) * DMODEL) + h * 64 + d4 * 4;
            Ks4[col][d4] = __ldg((const float4*)(Kp + off));
        }
    }
    // V tile: 48 cols x 32 float2
    for (int idx = tid; idx < CTILE * 32; idx += 256) {
        const int col = idx >> 5, l2 = idx & 31;
        if (colT0 + col < Lkv) {
            const size_t off = ((size_t)(b * Lkv + colT0 + col) * DMODEL) + h * 64 + l2 * 2;
            Vs2[col][l2] = __ldg((const float2*)(Vp + off));
        }
    }
    __syncthreads();

    // 8 steps x 2 queries per warp (one per half-warp)
    for (int step = 0; step < 8; step++) {
        const int cbase = c0 + wid * 16 + step * 2;
        const int c = cbase + half;

        const int fd = floordiv_s(SPAN - 1 - c, STRIDE);
        const int col = rlane - fd;
        const int row = c - STRIDE * col;
        const bool valid = (row >= 0) && (row < SPAN) && (col >= 0) && (col < Lkv);
        const int ii = min(max(col - colT0, 0), CTILE - 1);

        // 64-dim dot: 16 x (broadcast LDG.128 Q + LDS.128 K + 4 FFMA)
        const float4* Qrow = (const float4*)(Q + ((size_t)(b * Lq + c) * DMODEL) + h * 64);
        float acc = 0.f;
        #pragma unroll
        for (int d4 = 0; d4 < 16; d4++) {
            const float4 qv = __ldg(Qrow + d4);
            const float4 kv = Ks4[ii][d4];
            acc += qv.x * kv.x + qv.y * kv.y + qv.z * kv.z + qv.w * kv.w;
        }
        const float sc = valid ? acc * 0.125f : -1e30f;

        // softmax over the 16 lanes of this half-warp
        float m = sc;
        #pragma unroll
        for (int off = 8; off > 0; off >>= 1)
            m = fmaxf(m, __shfl_xor_sync(0xffffffffu, m, off));
        const float e = valid ? __expf(sc - m) : 0.f;
        float s = e;
        #pragma unroll
        for (int off = 8; off > 0; off >>= 1)
            s += __shfl_xor_sync(0xffffffffu, s, off);
        const float w = e / s;   // weight for key rlane of query c

        // V accumulation: all 32 lanes per query, dims (2*lane, 2*lane+1)
        #pragma unroll
        for (int qh = 0; qh < 2; qh++) {
            const int cq = cbase + qh;
            const int fdq = floordiv_s(SPAN - 1 - cq, STRIDE);
            float ox = 0.f, oy = 0.f;
            #pragma unroll
            for (int r = 0; r < R_SPAN; r++) {
                const float wr = __shfl_sync(0xffffffffu, w, qh * 16 + r);
                const int iir = min(max(r - fdq - colT0, 0), CTILE - 1);
                const float2 vv = Vs2[iir][lane];
                ox += wr * vv.x;
                oy += wr * vv.y;
            }
            // split-bf16 ctx write: dims (2*lane, 2*lane+1) as bfloat162
            __nv_bfloat16 hx, lx, hy, ly;
            split1(ox, hx, lx);
            split1(oy, hy, ly);
            __nv_bfloat16* base = ctxb + (size_t)(b * Lq + cq) * GK + h * DIM_V + 2 * lane;
            __nv_bfloat162 hp; hp.x = hx; hp.y = hy;
            __nv_bfloat162 lp; lp.x = lx; lp.y = ly;
            *(__nv_bfloat162*)(base) = hp;
            *(__nv_bfloat162*)(base + 512) = hp;
            *(__nv_bfloat162*)(base + 1024) = lp;
        }
    }
}

// ---------------------------------------------------------------------------
// Launch
// ---------------------------------------------------------------------------
extern "C" void kernel_launch(void* const* d_in, const int* in_sizes, int n_in,
                              void* d_out, int out_size) {
    const float* q    = (const float*)d_in[0];
    const float* k    = (const float*)d_in[1];
    const float* v    = (const float*)d_in[2];
    const float* Wq   = (const float*)d_in[3];
    const float* Wk   = (const float*)d_in[4];
    const float* Wv   = (const float*)d_in[5];
    const float* Wout = (const float*)d_in[6];
    float* out = (float*)d_out;

    const int Lq  = in_sizes[0] / (BATCH * DMODEL);   // 4096
    const int Lkv = in_sizes[1] / (BATCH * DMODEL);   // 1024
    const int Mq  = BATCH * Lq;    // 8192
    const int Mkv = BATCH * Lkv;   // 2048

    __nv_bfloat16 *gAb, *gKb, *gVb, *gWb;
    float *gQ, *gK, *gV;
    cudaGetSymbolAddress((void**)&gAb, g_Ab);
    cudaGetSymbolAddress((void**)&gKb, g_Kb);
    cudaGetSymbolAddress((void**)&gVb, g_Vb);
    cudaGetSymbolAddress((void**)&gWb, g_Wb4);
    cudaGetSymbolAddress((void**)&gQ, g_Q);
    cudaGetSymbolAddress((void**)&gK, g_K);
    cudaGetSymbolAddress((void**)&gV, g_V);

    cudaFuncSetAttribute(gemm_qkv, cudaFuncAttributeMaxDynamicSharedMemorySize, GEMM_SMEM);
    cudaFuncSetAttribute(gemm_one, cudaFuncAttributeMaxDynamicSharedMemorySize, GEMM_SMEM);

    split_wT_all<<<dim3(16, 16, 4), dim3(32, 32)>>>(Wq, Wk, Wv, Wout, gWb);

    const int tot = (Mq + 2 * Mkv) * 128;
    split_act_all<<<(tot + 255) / 256, 256>>>((const float4*)q, (const float4*)k,
                                              (const float4*)v, gAb, gKb, gVb, Mq, Mkv);

    gemm_qkv<<<384, 256, GEMM_SMEM>>>(gAb, gKb, gVb, gWb, gQ, gK, gV);

    sparse_attn_v2<<<dim3(Lq / QBLK, BATCH * HEAD_NUM), 256>>>(gQ, gK, gV, gAb, Lq, Lkv);

    gemm_one<<<dim3(4, Mq / 128), 256, GEMM_SMEM>>>(gAb, gWb + 3 * (size_t)WSTRIDE, out);
}